// round 8
// baseline (speedup 1.0000x reference)
#include <cuda_runtime.h>
#include <cuda_bf16.h>
#include <cfloat>
#include <cstdint>

#define BB 8
#define CC 64
#define NN 4096
#define OO 64
#define KNB 20
#define FULLMASK 0xffffffffu

// Scratch (device globals: allocation-free per harness rules)
__device__ float g_pd[134217728];   // [B*N, N] pairwise "distance", 537MB
__device__ float g_cmax[4194304];   // [B*N, 128] per-32-col-chunk max, 16MB
__device__ float g_sq[32768];       // [B*N] squared norms
__device__ float g_P[2097152];      // [B*N, O]  x·(W1-W2)^T
__device__ float g_Q[2097152];      // [B*N, O]  x·W2^T

#define LDM_X4(r0, r1, r2, r3, addr)                                         \
    asm volatile("ldmatrix.sync.aligned.m8n8.x4.shared.b16 {%0,%1,%2,%3}, [%4];" \
                 : "=r"(r0), "=r"(r1), "=r"(r2), "=r"(r3) : "r"(addr))

#define MMA16816(c, a, b0, b1)                                               \
    asm volatile("mma.sync.aligned.m16n8k16.row.col.f32.bf16.bf16.f32 "      \
                 "{%0,%1,%2,%3}, {%4,%5,%6,%7}, {%8,%9}, {%0,%1,%2,%3};"     \
                 : "+f"((c)[0]), "+f"((c)[1]), "+f"((c)[2]), "+f"((c)[3])    \
                 : "r"((a)[0]), "r"((a)[1]), "r"((a)[2]), "r"((a)[3]),       \
                   "r"(b0), "r"(b1))

// SMEM layout (bytes). 6 bf16 tiles [128 rows][64 k] = 16KB each.
#define SM_A0   0
#define SM_B0   49152
#define SM_SQN  98304
#define SM_SQM  98816
#define SM_TOT  99328
#define STAGE_PITCH 132   // floats; multiple of 4 so float4 accesses stay 16B-aligned

__device__ __forceinline__ uint32_t smem_u32(const void* p) {
    uint32_t a;
    asm("{ .reg .u64 t; cvta.to.shared.u64 t, %1; cvt.u32.u64 %0, t; }"
        : "=r"(a) : "l"(p));
    return a;
}

// ---------------------------------------------------------------------------
// Kernel 1: squared norms. sq[b,n] = sum_c x[b,c,n]^2
// ---------------------------------------------------------------------------
__global__ void sq_kernel(const float* __restrict__ x) {
    int t = blockIdx.x * blockDim.x + threadIdx.x;
    int b = t >> 12, n = t & 4095;
    const float* xp = x + (size_t)b * CC * NN + n;
    float s = 0.f;
    #pragma unroll
    for (int c = 0; c < CC; ++c) {
        float v = xp[(size_t)c * NN];
        s = fmaf(v, v, s);
    }
    g_sq[t] = s;
}

// ---------------------------------------------------------------------------
// Kernel 2: P = x·(W1-W2)^T, Q = x·W2^T
// ---------------------------------------------------------------------------
__global__ __launch_bounds__(256) void pq_kernel(const float* __restrict__ x,
                                                 const float* __restrict__ W) {
    __shared__ float Wa[CC][OO + 1];
    __shared__ float Wb[CC][OO + 1];
    __shared__ float xs[CC][4];
    int tid = threadIdx.x;
    #pragma unroll
    for (int i = 0; i < 16; ++i) {
        int fid = tid + i * 256;
        int o = fid >> 6, c = fid & 63;
        float w1 = W[o * 128 + c];
        float w2 = W[o * 128 + 64 + c];
        Wa[c][o] = w1 - w2;
        Wb[c][o] = w2;
    }
    int nbase = blockIdx.x * 4;
    int b = nbase >> 12;
    int nb = nbase & 4095;
    {
        int c = tid >> 2, j = tid & 3;
        xs[c][j] = x[(size_t)b * CC * NN + (size_t)c * NN + nb + j];
    }
    __syncthreads();
    int o = tid & 63, nl = tid >> 6;
    float p = 0.f, q = 0.f;
    #pragma unroll
    for (int c = 0; c < CC; ++c) {
        float xv = xs[c][nl];
        p = fmaf(xv, Wa[c][o], p);
        q = fmaf(xv, Wb[c][o], q);
    }
    size_t g = (size_t)(nbase + nl);
    g_P[g * OO + o] = p;
    g_Q[g * OO + o] = q;
}

// ---------------------------------------------------------------------------
// Kernel 3: pd via HMMA (mma.sync bf16, 3-way split, 6 terms), triangular
// grid, mirror store, per-32-col chunkmax.
// Tiles in smem: [128 pts][64 k] bf16, 128B rows, XOR-16B swizzle.
// ---------------------------------------------------------------------------
__global__ __launch_bounds__(256, 2) void pd_mma(const float* __restrict__ x,
                                                 int b) {
    extern __shared__ char sm[];
    uint32_t sb = smem_u32(sm);
    int tid = threadIdx.x, lane = tid & 31, wid = tid >> 5;

    // tile decode: (nt <= mt), t = mt(mt+1)/2 + nt
    int t = blockIdx.x;
    int mt = (int)((sqrtf(8.f * (float)t + 1.f) - 1.f) * 0.5f);
    while ((mt + 1) * (mt + 2) / 2 <= t) ++mt;
    while (mt * (mt + 1) / 2 > t) --mt;
    int nt = t - mt * (mt + 1) / 2;
    int n0 = nt * 128, m0 = mt * 128;

    // ---- split-load both tiles into h/m/l bf16 smem (swizzled)
    const float* xb = x + (size_t)b * CC * NN;
    {
        int side = tid >> 7;             // 0: A tile (n-side), 1: B tile
        int row  = tid & 127;
        int p0 = side ? m0 : n0;
        char* hb = sm + (side ? SM_B0 : SM_A0);
        #pragma unroll 8
        for (int c = 0; c < CC; c += 2) {
            float v0 = xb[(size_t)c * NN + p0 + row];
            float v1 = xb[(size_t)(c + 1) * NN + p0 + row];
            __nv_bfloat16 h0 = __float2bfloat16(v0), h1 = __float2bfloat16(v1);
            float r0 = v0 - __bfloat162float(h0), r1 = v1 - __bfloat162float(h1);
            __nv_bfloat16 q0 = __float2bfloat16(r0), q1 = __float2bfloat16(r1);
            float s0 = r0 - __bfloat162float(q0), s1 = r1 - __bfloat162float(q1);
            __nv_bfloat16 l0 = __float2bfloat16(s0), l1 = __float2bfloat16(s1);
            uint32_t off = (uint32_t)(row * 128 + c * 2);
            off = off ^ ((off >> 3) & 0x70);
            __nv_bfloat162 hh; hh.x = h0; hh.y = h1;
            __nv_bfloat162 mm; mm.x = q0; mm.y = q1;
            __nv_bfloat162 ll; ll.x = l0; ll.y = l1;
            *(__nv_bfloat162*)(hb + off)         = hh;
            *(__nv_bfloat162*)(hb + 16384 + off) = mm;
            *(__nv_bfloat162*)(hb + 32768 + off) = ll;
        }
    }
    if (tid < 128)       ((float*)(sm + SM_SQN))[tid]       = g_sq[b * NN + n0 + tid];
    else                 ((float*)(sm + SM_SQM))[tid - 128] = g_sq[b * NN + m0 + (tid - 128)];
    __syncthreads();

    // ---- warp tiling: 2x4 warps, warp tile 64 rows x 32 cols
    int wr = wid >> 2, wc = wid & 3;
    float acc[4][4][4];
    #pragma unroll
    for (int mi = 0; mi < 4; ++mi)
        #pragma unroll
        for (int ni = 0; ni < 4; ++ni)
            #pragma unroll
            for (int q = 0; q < 4; ++q) acc[mi][ni][q] = 0.f;

    // per-lane ldmatrix address components
    int gA = lane >> 3;
    int rowA_add = (gA & 1) * 8 + (lane & 7);     // within m16 block
    int kA_add   = (gA >> 1) * 16;                // byte offset within k16
    uint32_t xorA = (uint32_t)(rowA_add & 7) << 4;
    int gB = lane >> 3;
    int rowB_add = (gB >> 1) * 8 + (lane & 7);    // within n16 block
    int kB_add   = (gB & 1) * 16;
    uint32_t xorB = (uint32_t)(rowB_add & 7) << 4;

    #pragma unroll
    for (int av = 0; av < 3; ++av) {
        uint32_t baseA = sb + SM_A0 + av * 16384;
        #pragma unroll
        for (int ks = 0; ks < 4; ++ks) {
            int kb = ks * 32;
            uint32_t afr[4][4];
            #pragma unroll
            for (int mi = 0; mi < 4; ++mi) {
                int row = wr * 64 + mi * 16 + rowA_add;
                uint32_t addr = (baseA + (uint32_t)(row * 128 + kb + kA_add)) ^ xorA;
                LDM_X4(afr[mi][0], afr[mi][1], afr[mi][2], afr[mi][3], addr);
            }
            #pragma unroll
            for (int bv = 0; bv < 3; ++bv) {
                if (av + bv > 2) break;
                uint32_t baseB = sb + SM_B0 + bv * 16384;
                uint32_t bfr[4][2];
                #pragma unroll
                for (int np = 0; np < 2; ++np) {
                    int row = wc * 32 + np * 16 + rowB_add;
                    uint32_t addr = (baseB + (uint32_t)(row * 128 + kb + kB_add)) ^ xorB;
                    LDM_X4(bfr[np * 2][0], bfr[np * 2][1],
                           bfr[np * 2 + 1][0], bfr[np * 2 + 1][1], addr);
                }
                #pragma unroll
                for (int mi = 0; mi < 4; ++mi)
                    #pragma unroll
                    for (int ni = 0; ni < 4; ++ni)
                        MMA16816(acc[mi][ni], afr[mi], bfr[ni][0], bfr[ni][1]);
            }
        }
    }
    __syncthreads();   // all warps done reading operand smem

    // ---- stage res = 2*acc - sqn - sqm into smem [128][STAGE_PITCH]
    const float* sqn = (const float*)(sm + SM_SQN);
    const float* sqm = (const float*)(sm + SM_SQM);
    float* stage = (float*)sm;
    {
        int g = lane >> 2, tg = lane & 3;
        #pragma unroll
        for (int mi = 0; mi < 4; ++mi) {
            int r0 = wr * 64 + mi * 16 + g;
            float sn0 = sqn[r0], sn1 = sqn[r0 + 8];
            #pragma unroll
            for (int ni = 0; ni < 4; ++ni) {
                int col = wc * 32 + ni * 8 + tg * 2;
                float sm0 = sqm[col], sm1 = sqm[col + 1];
                float2 u, v;
                u.x = 2.f * acc[mi][ni][0] - sn0 - sm0;
                u.y = 2.f * acc[mi][ni][1] - sn0 - sm1;
                v.x = 2.f * acc[mi][ni][2] - sn1 - sm0;
                v.y = 2.f * acc[mi][ni][3] - sn1 - sm1;
                *(float2*)&stage[r0 * STAGE_PITCH + col]       = u;
                *(float2*)&stage[(r0 + 8) * STAGE_PITCH + col] = v;
            }
        }
    }
    __syncthreads();

    // ---- copy-out: normal rows + chunkmax
    int row = tid >> 1, half = tid & 1;
    float* outp = g_pd + ((size_t)(b * NN + n0 + row)) * NN + m0 + half * 64;
    float* cmn  = g_cmax + (size_t)(b * NN + n0 + row) * 128 + mt * 4 + half * 2;
    {
        float c0 = -FLT_MAX, c1 = -FLT_MAX;
        #pragma unroll
        for (int q = 0; q < 16; ++q) {
            float4 f = *(float4*)&stage[row * STAGE_PITCH + half * 64 + q * 4];
            float mx = fmaxf(fmaxf(f.x, f.y), fmaxf(f.z, f.w));
            if (q < 8) c0 = fmaxf(c0, mx); else c1 = fmaxf(c1, mx);
            *(float4*)&outp[q * 4] = f;
        }
        cmn[0] = c0;
        cmn[1] = c1;
    }

    // ---- mirror (skip on diagonal): transposed read from stage
    if (nt != mt) {
        int mr = row;                 // mirror row = original col index
        float* outq = g_pd + ((size_t)(b * NN + m0 + mr)) * NN + n0 + half * 64;
        float* cmm  = g_cmax + (size_t)(b * NN + m0 + mr) * 128 + nt * 4 + half * 2;
        float c0 = -FLT_MAX, c1 = -FLT_MAX;
        #pragma unroll 4
        for (int q = 0; q < 16; ++q) {
            float4 f;
            int jb = half * 64 + q * 4;
            f.x = stage[(jb + 0) * STAGE_PITCH + mr];
            f.y = stage[(jb + 1) * STAGE_PITCH + mr];
            f.z = stage[(jb + 2) * STAGE_PITCH + mr];
            f.w = stage[(jb + 3) * STAGE_PITCH + mr];
            float mx = fmaxf(fmaxf(f.x, f.y), fmaxf(f.z, f.w));
            if (q < 8) c0 = fmaxf(c0, mx); else c1 = fmaxf(c1, mx);
            *(float4*)&outq[q * 4] = f;
        }
        cmm[0] = c0;
        cmm[1] = c1;
    }
}

// ---------------------------------------------------------------------------
// Kernel 4: warp-per-row top-20 via chunkmax gating, fused epilogue.
// Per-batch launch (512 CTAs) so pd[b] is L2-hot.
// ---------------------------------------------------------------------------
__global__ __launch_bounds__(256) void topk_fused(
    const float* __restrict__ gamma, const float* __restrict__ beta,
    const float* __restrict__ rmean, const float* __restrict__ rvar,
    float* __restrict__ out, int b)
{
    int warp = threadIdx.x >> 5, lane = threadIdx.x & 31;
    int n = blockIdx.x * 8 + warp;
    int row = b * NN + n;

    const float* cmrow = g_cmax + (size_t)row * 128;
    float cm[4];
    #pragma unroll
    for (int j = 0; j < 4; ++j) cm[j] = __ldg(&cmrow[j * 32 + lane]);
    float lmax = fmaxf(fmaxf(cm[0], cm[1]), fmaxf(cm[2], cm[3]));

    float s = lmax;
    #pragma unroll
    for (int k2 = 2; k2 <= 32; k2 <<= 1) {
        #pragma unroll
        for (int j2 = k2 >> 1; j2 > 0; j2 >>= 1) {
            float o = __shfl_xor_sync(FULLMASK, s, j2);
            bool dirAsc = ((lane & k2) == 0);
            bool upper  = ((lane & j2) == 0);
            float mn = fminf(s, o), mx = fmaxf(s, o);
            s = (dirAsc == upper) ? mn : mx;
        }
    }
    float T0 = __shfl_sync(FULLMASK, s, 32 - KNB);

    float lv = -FLT_MAX;
    int   li = 0;
    float vmin = -FLT_MAX;
    int   minpos = 0;
    const float* rowf = g_pd + (size_t)row * NN;

    #pragma unroll
    for (int j = 0; j < 4; ++j) {
        unsigned cmask = __ballot_sync(FULLMASK, cm[j] >= T0);
        while (cmask) {
            int q = __ffs(cmask) - 1;
            cmask &= cmask - 1;
            float cmv = __shfl_sync(FULLMASK, cm[j], q);
            if (cmv <= vmin && vmin > -FLT_MAX) continue;
            int chunk = j * 32 + q;
            float v = __ldg(&rowf[chunk * 32 + lane]);
            unsigned m = __ballot_sync(FULLMASK, v >= T0 && v > vmin);
            while (m) {
                int lead = __ffs(m) - 1;
                float cv = __shfl_sync(FULLMASK, v, lead);
                int   ci = chunk * 32 + lead;
                if (lane == minpos) { lv = cv; li = ci; }
                float tt = (lane < KNB) ? lv : FLT_MAX;
                #pragma unroll
                for (int off = 16; off; off >>= 1)
                    tt = fminf(tt, __shfl_xor_sync(FULLMASK, tt, off));
                vmin = tt;
                minpos = __ffs(__ballot_sync(FULLMASK, lane < KNB && lv == vmin)) - 1;
                m &= ~(1u << lead);
                m &= __ballot_sync(FULLMASK, v > vmin);
            }
        }
    }

    float sc1 = gamma[lane]      * rsqrtf(rvar[lane]      + 1e-5f);
    float sc2 = gamma[lane + 32] * rsqrtf(rvar[lane + 32] + 1e-5f);
    float bi1 = beta[lane]      - rmean[lane]      * sc1;
    float bi2 = beta[lane + 32] - rmean[lane + 32] * sc2;
    float p1 = g_P[(size_t)row * OO + lane];
    float p2 = g_P[(size_t)row * OO + lane + 32];
    const float* Qb = g_Q + (size_t)b * NN * OO;

    float m1 = -FLT_MAX, m2 = -FLT_MAX;
    #pragma unroll
    for (int kk = 0; kk < KNB; ++kk) {
        int nid = __shfl_sync(FULLMASK, li, kk);
        const float* Qr = Qb + (size_t)nid * OO;
        float y1 = (p1 + __ldg(&Qr[lane]))      * sc1 + bi1;
        float y2 = (p2 + __ldg(&Qr[lane + 32])) * sc2 + bi2;
        y1 = (y1 >= 0.f) ? y1 : 0.2f * y1;
        y2 = (y2 >= 0.f) ? y2 : 0.2f * y2;
        m1 = fmaxf(m1, y1);
        m2 = fmaxf(m2, y2);
    }
    out[((size_t)b * OO + lane)      * NN + n] = m1;
    out[((size_t)b * OO + lane + 32) * NN + n] = m2;
}

// ---------------------------------------------------------------------------
extern "C" void kernel_launch(void* const* d_in, const int* in_sizes, int n_in,
                              void* d_out, int out_size) {
    const float* x     = (const float*)d_in[0];
    const float* W     = (const float*)d_in[1];
    const float* gamma = (const float*)d_in[2];
    const float* beta  = (const float*)d_in[3];
    const float* rmean = (const float*)d_in[4];
    const float* rvar  = (const float*)d_in[5];
    float* out = (float*)d_out;

    static int inited = 0;
    if (!inited) {
        cudaFuncSetAttribute(pd_mma, cudaFuncAttributeMaxDynamicSharedMemorySize,
                             SM_TOT);
        inited = 1;
    }

    sq_kernel<<<128, 256>>>(x);
    pq_kernel<<<8192, 256>>>(x, W);
    for (int b = 0; b < BB; ++b) {
        pd_mma<<<528, 256, SM_TOT>>>(x, b);
        topk_fused<<<512, 256>>>(gamma, beta, rmean, rvar, out, b);
    }
}